// round 1
// baseline (speedup 1.0000x reference)
#include <cuda_runtime.h>
#include <math.h>

// Problem constants
#define B_ROWS 4096
#define HID    2048

constexpr int BM  = 128;   // rows per CTA
constexpr int BH  = 32;    // hidden columns per CTA (x4 gates = 128 C-cols)
constexpr int BN  = 128;   // C columns per CTA (col = h*4 + g)
constexpr int BK  = 16;    // K-tile
constexpr int AST = BM + 4;  // padded smem stride (132) to spread banks
constexpr int BST = BN + 4;  // padded smem stride (132)
constexpr int NT      = 4096 / BK;  // 256 K-tiles total
constexpr int HALF_T  = 2048 / BK;  // 128: boundary between x/Wx and hx/Wh

__device__ __forceinline__ float sigm(float v) { return 1.f / (1.f + __expf(-v)); }

__global__ __launch_bounds__(256, 2)
void lstm_cell_kernel(const float* __restrict__ x,
                      const float* __restrict__ hx,
                      const float* __restrict__ cx,
                      const float* __restrict__ Wx,
                      const float* __restrict__ bx,
                      const float* __restrict__ Wh,
                      const float* __restrict__ bh,
                      float* __restrict__ out)
{
    __shared__ float As[2][BK][AST];  // A tile, transposed: As[k][row]
    __shared__ float Bs[2][BK][BST];  // W tile, transposed: Bs[k][col], col = h*4+g

    const int tid = threadIdx.x;
    const int m0  = blockIdx.y * BM;   // row-tile origin
    const int j0  = blockIdx.x * BH;   // hidden-col tile origin

    // ---- per-thread load descriptors (2 float4 for A, 2 for B per K-tile) ----
    int rowA[2], kA[2], colB[2];
    size_t aoff[2], boff[2];
#pragma unroll
    for (int i = 0; i < 2; i++) {
        int idx  = tid + i * 256;        // 512 float4 per 128x16 tile
        rowA[i]  = idx >> 2;             // 0..127
        kA[i]    = (idx & 3) << 2;       // 0,4,8,12
        aoff[i]  = (size_t)(m0 + rowA[i]) * 2048 + kA[i];
        colB[i]  = idx >> 2;             // C column 0..127
        int g    = colB[i] & 3;          // gate
        int h    = colB[i] >> 2;         // hidden offset within tile
        boff[i]  = (size_t)(g * HID + j0 + h) * 2048 + kA[i];
    }

    // ---- micro-tile mapping: 16x16 thread grid, 8x8 accum each ----
    const int trow = tid >> 4, tcol = tid & 15;
    const int r0 = trow * 8, c0 = tcol * 8;

    float acc[8][8];
#pragma unroll
    for (int i = 0; i < 8; i++)
#pragma unroll
        for (int j = 0; j < 8; j++) acc[i][j] = 0.f;

    // ---- prologue: tile 0 straight to smem buffer 0 ----
    {
#pragma unroll
        for (int i = 0; i < 2; i++) {
            float4 va = *(const float4*)(x  + aoff[i]);
            float4 vb = *(const float4*)(Wx + boff[i]);
            As[0][kA[i] + 0][rowA[i]] = va.x;
            As[0][kA[i] + 1][rowA[i]] = va.y;
            As[0][kA[i] + 2][rowA[i]] = va.z;
            As[0][kA[i] + 3][rowA[i]] = va.w;
            Bs[0][kA[i] + 0][colB[i]] = vb.x;
            Bs[0][kA[i] + 1][colB[i]] = vb.y;
            Bs[0][kA[i] + 2][colB[i]] = vb.z;
            Bs[0][kA[i] + 3][colB[i]] = vb.w;
        }
    }
    __syncthreads();

    // ---- mainloop: double-buffered, register-staged prefetch ----
    int buf = 0;
    for (int kt = 0; kt < NT; kt++) {
        float4 sa[2], sb[2];
        if (kt + 1 < NT) {
            const int nk = kt + 1;
            const float* ap = (nk < HALF_T) ? x  : hx;
            const float* wp = (nk < HALF_T) ? Wx : Wh;
            const int kofs  = ((nk < HALF_T) ? nk : (nk - HALF_T)) * BK;
#pragma unroll
            for (int i = 0; i < 2; i++) {
                sa[i] = *(const float4*)(ap + aoff[i] + kofs);
                sb[i] = *(const float4*)(wp + boff[i] + kofs);
            }
        }

#pragma unroll
        for (int k = 0; k < BK; k++) {
            float a[8], b[8];
            *(float4*)&a[0] = *(const float4*)&As[buf][k][r0];
            *(float4*)&a[4] = *(const float4*)&As[buf][k][r0 + 4];
            *(float4*)&b[0] = *(const float4*)&Bs[buf][k][c0];
            *(float4*)&b[4] = *(const float4*)&Bs[buf][k][c0 + 4];
#pragma unroll
            for (int i = 0; i < 8; i++)
#pragma unroll
                for (int j = 0; j < 8; j++)
                    acc[i][j] = fmaf(a[i], b[j], acc[i][j]);
        }

        if (kt + 1 < NT) {
            const int nb = buf ^ 1;
#pragma unroll
            for (int i = 0; i < 2; i++) {
                As[nb][kA[i] + 0][rowA[i]] = sa[i].x;
                As[nb][kA[i] + 1][rowA[i]] = sa[i].y;
                As[nb][kA[i] + 2][rowA[i]] = sa[i].z;
                As[nb][kA[i] + 3][rowA[i]] = sa[i].w;
                Bs[nb][kA[i] + 0][colB[i]] = sb[i].x;
                Bs[nb][kA[i] + 1][colB[i]] = sb[i].y;
                Bs[nb][kA[i] + 2][colB[i]] = sb[i].z;
                Bs[nb][kA[i] + 3][colB[i]] = sb[i].w;
            }
            buf = nb;
            __syncthreads();
        }
    }

    // ---- fused LSTM epilogue ----
    // thread's C-cols: c = tcol*8 + jj, jj = hh*4 + g  ->  hidden j = j0 + tcol*2 + hh
    float bias[2][4];
#pragma unroll
    for (int hh = 0; hh < 2; hh++) {
        const int j = j0 + tcol * 2 + hh;
#pragma unroll
        for (int g = 0; g < 4; g++)
            bias[hh][g] = bx[g * HID + j] + bh[g * HID + j];
    }

#pragma unroll
    for (int i = 0; i < 8; i++) {
        const int row = m0 + r0 + i;
#pragma unroll
        for (int hh = 0; hh < 2; hh++) {
            const int j = j0 + tcol * 2 + hh;
            const float f_  = sigm (acc[i][hh * 4 + 0] + bias[hh][0]);
            const float i_  = sigm (acc[i][hh * 4 + 1] + bias[hh][1]);
            const float c_  = tanhf(acc[i][hh * 4 + 2] + bias[hh][2]);
            const float o_  = sigm (acc[i][hh * 4 + 3] + bias[hh][3]);
            const float cv  = cx[(size_t)row * HID + j];
            const float cy  = f_ * cv + i_ * c_;
            const float hy  = o_ * tanhf(cy);
            out[(size_t)row * HID + j] = hy;                                 // hy block
            out[(size_t)B_ROWS * HID + (size_t)row * HID + j] = cy;          // cy block
        }
    }
}

extern "C" void kernel_launch(void* const* d_in, const int* in_sizes, int n_in,
                              void* d_out, int out_size)
{
    // metadata order: input, hx, cx, W_x2h, b_x2h, W_h2h, b_h2h
    const float* x  = (const float*)d_in[0];
    const float* hx = (const float*)d_in[1];
    const float* cx = (const float*)d_in[2];
    const float* Wx = (const float*)d_in[3];
    const float* bx = (const float*)d_in[4];
    const float* Wh = (const float*)d_in[5];
    const float* bh = (const float*)d_in[6];
    float* out = (float*)d_out;

    dim3 grid(HID / BH, B_ROWS / BM);  // (64, 32) = 2048 CTAs
    lstm_cell_kernel<<<grid, 256>>>(x, hx, cx, Wx, bx, Wh, bh, out);
}

// round 4
// speedup vs baseline: 2.5156x; 2.5156x over previous
#include <cuda_runtime.h>
#include <cstdint>
#include <math.h>

// ---------------- problem constants ----------------
#define HID    2048
#define BROWS  4096
#define KHALF  2048           // K extent of each half (x/Wx vs hx/Wh)

constexpr int BM = 128;       // rows per CTA
constexpr int BN = 128;       // C cols per CTA (col = h*4 + g -> 32 hidden cols)
constexpr int BK = 32;        // K per smem tile (4 mma k8 steps)
constexpr int NT = 4096 / BK;        // 128 k-tiles
constexpr int HALF_T = 2048 / BK;    // 64
constexpr int NUM_NT = (4 * HID) / BN;  // 64 n-tiles
constexpr int GROUP_M = 8;

// ---------------- smem layout ----------------
constexpr int TILE_BYTES = BM * BK * 4;      // 16 KB
constexpr int SM_A0 = 1024;
constexpr int SM_A1 = SM_A0 + TILE_BYTES;
constexpr int SM_B0 = SM_A1 + TILE_BYTES;
constexpr int SM_B1 = SM_B0 + TILE_BYTES;    // mainloop ends at 66560
constexpr int CSTRIDE = 132;                 // epilogue C stride (floats)
constexpr int SM_C = 1024;                   // epilogue reuses tile region
constexpr int SMEM_TOTAL = 1024 + BM * CSTRIDE * 4;  // 68608

#define SWZ(o) ((o) ^ (((o) >> 3) & 0x70))   // SW128 swizzle

__device__ __forceinline__ uint32_t tf32r(float x) {   // round-to-nearest tf32
    uint32_t y;
    asm("cvt.rna.tf32.f32 %0, %1;" : "=r"(y) : "f"(x));
    return y;
}
__device__ __forceinline__ float sigm(float v) { return 1.f / (1.f + __expf(-v)); }

// smem fragment address: row-major 128B rows, swizzle folds to per-row XOR
__device__ __forceinline__ const float* frag_ptr(const uint8_t* tile, int r, int kbytes) {
    return (const float*)(tile + r * 128 + (kbytes ^ ((r & 7) << 4)));
}

__device__ __forceinline__ void mma_tf32(float& c0, float& c1, float& c2, float& c3,
                                         uint32_t a0, uint32_t a1, uint32_t a2, uint32_t a3,
                                         uint32_t b0, uint32_t b1) {
    asm volatile(
        "mma.sync.aligned.m16n8k8.row.col.f32.tf32.tf32.f32 "
        "{%0,%1,%2,%3}, {%4,%5,%6,%7}, {%8,%9}, {%0,%1,%2,%3};"
        : "+f"(c0), "+f"(c1), "+f"(c2), "+f"(c3)
        : "r"(a0), "r"(a1), "r"(a2), "r"(a3), "r"(b0), "r"(b1));
}

// ---------------- kernel ----------------
__global__ __launch_bounds__(256, 1)
void lstm_mma_kernel(const float* __restrict__ x,
                     const float* __restrict__ hx,
                     const float* __restrict__ cx,
                     const float* __restrict__ Wx,
                     const float* __restrict__ bx,
                     const float* __restrict__ Wh,
                     const float* __restrict__ bh,
                     float* __restrict__ out)
{
    extern __shared__ __align__(1024) uint8_t smem[];
    const int tid  = threadIdx.x;
    const int wid  = tid >> 5;
    const int lane = tid & 31;
    const int g    = lane >> 2;   // group id (0..7)
    const int tig  = lane & 3;    // thread in group

    // ---- CTA tile mapping (GROUP_M swizzle for L2 reuse of W) ----
    int bid    = blockIdx.x;
    int group  = bid / (GROUP_M * NUM_NT);
    int rem    = bid % (GROUP_M * NUM_NT);
    int m_tile = group * GROUP_M + (rem % GROUP_M);
    int n_tile = rem / GROUP_M;
    const int m0 = m_tile * BM;
    const int j0 = n_tile * (BN / 4);   // 32 hidden cols per CTA

    // ---- per-thread load descriptors: 4 float4 per operand per k-tile ----
    size_t aoff[4], boff[4];
    uint32_t sts_off[4];
#pragma unroll
    for (int i = 0; i < 4; i++) {
        int idx = tid + i * 256;
        int row = idx >> 3;          // 0..127 (M row for A, C col for B)
        int kq  = idx & 7;           // float4 slot along K
        aoff[i] = (size_t)(m0 + row) * KHALF + kq * 4;
        int gg = row & 3, jl = row >> 2;
        boff[i] = ((size_t)(gg * HID + j0 + jl)) * KHALF + kq * 4;
        sts_off[i] = SWZ((uint32_t)(row * 128 + kq * 16));
    }

    const int smA[2] = {SM_A0, SM_A1};
    const int smB[2] = {SM_B0, SM_B1};

    auto ldg_tile = [&](int t, float4* A, float4* Bv) {
        const float* ap = (t < HALF_T) ? x  : hx;
        const float* wp = (t < HALF_T) ? Wx : Wh;
        const int kofs  = ((t < HALF_T) ? t : (t - HALF_T)) * BK;
#pragma unroll
        for (int i = 0; i < 4; i++) {
            A[i]  = *(const float4*)(ap + aoff[i] + kofs);
            Bv[i] = *(const float4*)(wp + boff[i] + kofs);
        }
    };
    auto sts_tile = [&](int buf, const float4* A, const float4* Bv) {
#pragma unroll
        for (int i = 0; i < 4; i++) {
            uint4 va = { tf32r(A[i].x),  tf32r(A[i].y),  tf32r(A[i].z),  tf32r(A[i].w)  };
            uint4 vb = { tf32r(Bv[i].x), tf32r(Bv[i].y), tf32r(Bv[i].z), tf32r(Bv[i].w) };
            *(uint4*)(smem + smA[buf] + sts_off[i]) = va;
            *(uint4*)(smem + smB[buf] + sts_off[i]) = vb;
        }
    };

    // ---- warp tile: 2(M) x 4(N), 64x32 per warp ----
    const int wm = (wid >> 2) * 64;
    const int wn = (wid & 3) * 32;

    float acc[4][4][4];
#pragma unroll
    for (int mi = 0; mi < 4; mi++)
#pragma unroll
        for (int ni = 0; ni < 4; ni++)
#pragma unroll
            for (int q = 0; q < 4; q++) acc[mi][ni][q] = 0.f;

    // ---- prologue ----
    float4 stgA[4], stgB[4];
    ldg_tile(0, stgA, stgB);
    sts_tile(0, stgA, stgB);
    __syncthreads();

    // ---- mainloop ----
    for (int t = 0; t < NT; t++) {
        const int buf = t & 1;
        if (t + 1 < NT) ldg_tile(t + 1, stgA, stgB);

        const uint8_t* At = smem + smA[buf];
        const uint8_t* Bt = smem + smB[buf];

#pragma unroll
        for (int kk = 0; kk < 4; kk++) {
            const int kb0 = kk * 32 + tig * 4;      // byte offset of col tig
            uint32_t a[4][4], b[4][2];
#pragma unroll
            for (int mi = 0; mi < 4; mi++) {
                const int r1 = wm + mi * 16 + g;
                const int r2 = r1 + 8;
                a[mi][0] = __float_as_uint(*frag_ptr((const uint8_t*)At, r1, kb0));
                a[mi][1] = __float_as_uint(*frag_ptr((const uint8_t*)At, r2, kb0));
                a[mi][2] = __float_as_uint(*frag_ptr((const uint8_t*)At, r1, kb0 + 16));
                a[mi][3] = __float_as_uint(*frag_ptr((const uint8_t*)At, r2, kb0 + 16));
            }
#pragma unroll
            for (int ni = 0; ni < 4; ni++) {
                const int c = wn + ni * 8 + g;
                b[ni][0] = __float_as_uint(*frag_ptr((const uint8_t*)Bt, c, kb0));
                b[ni][1] = __float_as_uint(*frag_ptr((const uint8_t*)Bt, c, kb0 + 16));
            }
#pragma unroll
            for (int mi = 0; mi < 4; mi++)
#pragma unroll
                for (int ni = 0; ni < 4; ni++)
                    mma_tf32(acc[mi][ni][0], acc[mi][ni][1], acc[mi][ni][2], acc[mi][ni][3],
                             a[mi][0], a[mi][1], a[mi][2], a[mi][3],
                             b[ni][0], b[ni][1]);
        }

        if (t + 1 < NT) {
            sts_tile(buf ^ 1, stgA, stgB);
            __syncthreads();
        }
    }

    // ---- epilogue: stage C through smem, then fused LSTM math ----
    __syncthreads();   // all warps done reading A/B tiles
    float* Cs = (float*)(smem + SM_C);
#pragma unroll
    for (int mi = 0; mi < 4; mi++) {
#pragma unroll
        for (int ni = 0; ni < 4; ni++) {
            const int r1 = wm + mi * 16 + g;
            const int c0 = wn + ni * 8 + tig * 2;
            *(float2*)(Cs + r1 * CSTRIDE + c0)       = make_float2(acc[mi][ni][0], acc[mi][ni][1]);
            *(float2*)(Cs + (r1 + 8) * CSTRIDE + c0) = make_float2(acc[mi][ni][2], acc[mi][ni][3]);
        }
    }
    __syncthreads();

    // biases for this thread's hidden column (h = lane)
    const int j = j0 + lane;
    const float bs0 = bx[0 * HID + j] + bh[0 * HID + j];
    const float bs1 = bx[1 * HID + j] + bh[1 * HID + j];
    const float bs2 = bx[2 * HID + j] + bh[2 * HID + j];
    const float bs3 = bx[3 * HID + j] + bh[3 * HID + j];

#pragma unroll
    for (int i = 0; i < 16; i++) {
        const int rl  = i * 8 + wid;          // local row 0..127
        const int row = m0 + rl;
        const float4 gv = *(const float4*)(Cs + rl * CSTRIDE + lane * 4);
        const float f_ = sigm (gv.x + bs0);
        const float i_ = sigm (gv.y + bs1);
        const float c_ = tanhf(gv.z + bs2);
        const float o_ = sigm (gv.w + bs3);
        const float cv = cx[(size_t)row * HID + j];
        const float cy = f_ * cv + i_ * c_;
        const float hy = o_ * tanhf(cy);
        out[(size_t)row * HID + j] = hy;
        out[(size_t)BROWS * HID + (size_t)row * HID + j] = cy;
    }
}

extern "C" void kernel_launch(void* const* d_in, const int* in_sizes, int n_in,
                              void* d_out, int out_size)
{
    const float* x  = (const float*)d_in[0];
    const float* hx = (const float*)d_in[1];
    const float* cx = (const float*)d_in[2];
    const float* Wx = (const float*)d_in[3];
    const float* bx = (const float*)d_in[4];
    const float* Wh = (const float*)d_in[5];
    const float* bh = (const float*)d_in[6];
    float* out = (float*)d_out;

    cudaFuncSetAttribute(lstm_mma_kernel,
                         cudaFuncAttributeMaxDynamicSharedMemorySize, SMEM_TOTAL);
    const int grid = (BROWS / BM) * NUM_NT;   // 2048
    lstm_mma_kernel<<<grid, 256, SMEM_TOTAL>>>(x, hx, cx, Wx, bx, Wh, bh, out);
}